// round 11
// baseline (speedup 1.0000x reference)
#include <cuda_runtime.h>

#define Bn 4096
#define P1 148            // 148 SMs x 1 block of 1024 (32 warps/SM, same occ)
#define T1 1024

// Scratch (fully rewritten every launch; g_done returns to 0 every launch)
__device__ float g_rs1[Bn];
__device__ float g_rs2[Bn];
__device__ float g_cp1[(size_t)P1 * Bn];   // 2.42 MB col partials of E
__device__ float g_cp2[(size_t)P1 * Bn];   // 2.42 MB col partials of E^2
__device__ float g_part[128];
__device__ unsigned g_done;

__device__ __forceinline__ float ex2f(float x) {
    float r; asm("ex2.approx.ftz.f32 %0, %1;" : "=f"(r) : "f"(x)); return r;
}
#define SCALE 2.8853900817779268f          // (1/t)/ln2, t = 0.5

// Pass 1: block bid owns rows {bid + k*148} (28 rows for bid<100, else 27)
// and columns 4t..4t+3 per thread. One float4 load per thread per row;
// row pairs + prefetch; column sums fully in registers -> one float4 store.
__global__ void __launch_bounds__(T1, 1) k1_sums(const float* __restrict__ L) {
    const int t = threadIdx.x;
    const int bid = blockIdx.x;
    const int warp = t >> 5, lane = t & 31;
    const int R = (bid < 100) ? 28 : 27;   // 100*28 + 48*27 = 4096

    float c1[4], c2[4];
#pragma unroll
    for (int j = 0; j < 4; j++) { c1[j] = 0.f; c2[j] = 0.f; }

    __shared__ float s1[32][28];
    __shared__ float s2[32][28];

    // prologue: row pair 0
    float4 a0 = __ldcs((const float4*)(L + (size_t)bid * Bn) + t);
    float4 b0 = __ldcs((const float4*)(L + (size_t)(bid + P1) * Bn) + t);

    int k = 0;
    for (; k + 2 <= R; k += 2) {
        const bool more = (k + 4 <= R);
        const int kn = more ? k + 2 : k;
        float4 na = __ldcs((const float4*)(L + (size_t)(bid + kn * P1) * Bn) + t);
        float4 nb = __ldcs((const float4*)(L + (size_t)(bid + (kn + 1) * P1) * Bn) + t);

        float xa[4] = {a0.x, a0.y, a0.z, a0.w};
        float xb[4] = {b0.x, b0.y, b0.z, b0.w};
        float ra1 = 0.f, ra2 = 0.f, rb1 = 0.f, rb2 = 0.f;
#pragma unroll
        for (int j = 0; j < 4; j++) {
            float ea = ex2f(xa[j] * SCALE);
            float eb = ex2f(xb[j] * SCALE);
            ra1 += ea;  rb1 += eb;
            c1[j] += ea + eb;
            ra2 = fmaf(ea, ea, ra2);
            rb2 = fmaf(eb, eb, rb2);
            c2[j] = fmaf(ea, ea, fmaf(eb, eb, c2[j]));
        }
#pragma unroll
        for (int o = 16; o > 0; o >>= 1) {
            ra1 += __shfl_xor_sync(~0u, ra1, o);
            ra2 += __shfl_xor_sync(~0u, ra2, o);
            rb1 += __shfl_xor_sync(~0u, rb1, o);
            rb2 += __shfl_xor_sync(~0u, rb2, o);
        }
        if (lane == 0) {
            s1[warp][k] = ra1;      s2[warp][k] = ra2;
            s1[warp][k + 1] = rb1;  s2[warp][k + 1] = rb2;
        }
        a0 = na; b0 = nb;
    }
    if (k < R) {  // tail row (R = 27 odd)
        float4 t0 = __ldcs((const float4*)(L + (size_t)(bid + k * P1) * Bn) + t);
        float x[4] = {t0.x, t0.y, t0.z, t0.w};
        float ra1 = 0.f, ra2 = 0.f;
#pragma unroll
        for (int j = 0; j < 4; j++) {
            float e = ex2f(x[j] * SCALE);
            ra1 += e; c1[j] += e;
            ra2 = fmaf(e, e, ra2);
            c2[j] = fmaf(e, e, c2[j]);
        }
#pragma unroll
        for (int o = 16; o > 0; o >>= 1) {
            ra1 += __shfl_xor_sync(~0u, ra1, o);
            ra2 += __shfl_xor_sync(~0u, ra2, o);
        }
        if (lane == 0) { s1[warp][k] = ra1; s2[warp][k] = ra2; }
    }
    __syncthreads();

    // warp w reduces row w's 32 per-warp partials (lane l reads warp l's)
    if (warp < R) {
        float a = s1[lane][warp];
        float b = s2[lane][warp];
#pragma unroll
        for (int o = 16; o > 0; o >>= 1) {
            a += __shfl_xor_sync(~0u, a, o);
            b += __shfl_xor_sync(~0u, b, o);
        }
        if (lane == 0) {
            g_rs1[bid + warp * P1] = a;
            g_rs2[bid + warp * P1] = b;
        }
    }

    ((float4*)(g_cp1 + (size_t)bid * Bn))[t] = make_float4(c1[0], c1[1], c1[2], c1[3]);
    ((float4*)(g_cp2 + (size_t)bid * Bn))[t] = make_float4(c2[0], c2[1], c2[2], c2[3]);
}

// Pass 2: reduce 148 stripes (4 unrolled + 1 predicated: 148 = 4*32 + 20),
// smem tree, per-row loss, last-block fixed-order final mean.
__global__ void __launch_bounds__(1024) k2_finalize(const float* __restrict__ L,
                                                    float* __restrict__ out) {
    const int tx = threadIdx.x & 31;
    const int g  = threadIdx.x >> 5;
    const int col = blockIdx.x * 32 + tx;

    float va[4], vb[4];
#pragma unroll
    for (int i = 0; i < 4; i++) {           // p = g + 32i (max 127 < 148)
        va[i] = __ldcg(&g_cp1[(size_t)(g + 32 * i) * Bn + col]);
        vb[i] = __ldcg(&g_cp2[(size_t)(g + 32 * i) * Bn + col]);
    }
    float ea = 0.f, eb = 0.f;
    if (g < 20) {                           // p = g + 128 (128..147)
        ea = __ldcg(&g_cp1[(size_t)(g + 128) * Bn + col]);
        eb = __ldcg(&g_cp2[(size_t)(g + 128) * Bn + col]);
    }
    float a = ea, b = eb;
#pragma unroll
    for (int i = 0; i < 4; i++) { a += va[i]; b += vb[i]; }

    __shared__ float sa[32][33];
    __shared__ float sb[32][33];
    sa[g][tx] = a;  sb[g][tx] = b;
    __syncthreads();

    if (threadIdx.x < 32) {
        float ra = 0.0f, rb = 0.0f;
#pragma unroll
        for (int w = 0; w < 32; w++) { ra += sa[w][tx]; rb += sb[w][tx]; }
        const int i = col;
        const float Nf    = 8190.0f;                         // 2B-2
        const float minNg = 8190.0f * 0.13533528323661270f;  // N*exp(-1/t)
        float d  = L[(size_t)i * Bn + i];
        float e  = ex2f(d * SCALE);
        float e2 = e * e;
        float S1 = g_rs1[i] + ra - 2.0f * e;
        float S2 = g_rs2[i] + rb - 2.0f * e2;
        float Ng = (Nf * S2 / S1 - 0.1f * Nf * e) * (1.0f / 0.9f);
        Ng = fmaxf(Ng, minNg);
        float loss = logf((e + Ng + 1e-8f) / e);
#pragma unroll
        for (int o = 16; o > 0; o >>= 1)
            loss += __shfl_xor_sync(~0u, loss, o);
        if (tx == 0) g_part[blockIdx.x] = loss;
    }

    __shared__ bool last;
    if (threadIdx.x == 0) {
        __threadfence();
        unsigned n = atomicAdd(&g_done, 1u);
        last = (n == 127u);
    }
    __syncthreads();
    if (last) {
        __threadfence();
        if (threadIdx.x < 128) {
            float v = __ldcg(&g_part[threadIdx.x]);
#pragma unroll
            for (int o = 16; o > 0; o >>= 1)
                v += __shfl_xor_sync(~0u, v, o);
            __shared__ float s[4];
            if ((threadIdx.x & 31) == 0) s[threadIdx.x >> 5] = v;
            __syncthreads();
            if (threadIdx.x == 0) {
                out[0] = (s[0] + s[1] + s[2] + s[3]) / (float)Bn;
                atomicExch(&g_done, 0u);
            }
        }
    }
}

extern "C" void kernel_launch(void* const* d_in, const int* in_sizes, int n_in,
                              void* d_out, int out_size) {
    const float* L = (const float*)d_in[0];
    float* out = (float*)d_out;
    k1_sums<<<P1, T1>>>(L);
    k2_finalize<<<128, 1024>>>(L, out);
}